// round 17
// baseline (speedup 1.0000x reference)
#include <cuda_runtime.h>
#include <cstdint>

// Depthwise1d: out[n,c,o] = sum_i x[n,c,i] * W[c,o,i] + b[c,o]
// N=4096, C=256, K=64, O=128, fp32.
//
// R15: champion inner tile (col-pair FFMA2, r=8 x c=8, xs LDS.32 broadcast +
// W LDS.128) with 512-thread CTA covering 256 rows: W staged once per 256
// rows (halved staging), half the blocks/barriers. Inner loop unchanged.

#define N_TOT   4096
#define C_TOT   256
#define K_IN    64
#define O_OUT   128
#define TILE_M  256
#define THREADS 512
#define XSTR    68       // Xsh row stride (floats)
#define WSTR    132      // Wsh k-row stride (floats)

// 8 MB scratch: W2g[c][k][o]
__device__ float W2g[C_TOT * K_IN * O_OUT];

__device__ __forceinline__ void ffma2(unsigned long long& d,
                                      unsigned long long a,
                                      unsigned long long b) {
    asm("fma.rn.f32x2 %0, %1, %2, %0;" : "+l"(d) : "l"(a), "l"(b));
}
__device__ __forceinline__ unsigned long long dup2(float w) {
    unsigned long long r;
    asm("mov.b64 %0, {%1, %1};" : "=l"(r) : "f"(w));
    return r;
}
__device__ __forceinline__ float2 unpack2(unsigned long long v) {
    float2 f;
    asm("mov.b64 {%0, %1}, %2;" : "=f"(f.x), "=f"(f.y) : "l"(v));
    return f;
}

// ---- Kernel A: W[c][o][k] -> W2g[c][k][o] (tiny) ----
__global__ __launch_bounds__(256)
void w_transpose(const float* __restrict__ W) {
    __shared__ float Wt[O_OUT * 68];       // [o][k] stride 68
    const int t = threadIdx.x;
    const int c = blockIdx.x;
#pragma unroll
    for (int j = 0; j < 8; ++j) {
        int idx = t + 256 * j;             // 0..2047
        int o = idx >> 4, q = idx & 15;
        float4 v = *(const float4*)(W + ((size_t)c * O_OUT + o) * K_IN + 4 * q);
        *(float4*)&Wt[o * 68 + 4 * q] = v;
    }
    __syncthreads();
    float* dst = W2g + (size_t)c * K_IN * O_OUT;
#pragma unroll
    for (int j = 0; j < 32; ++j) {
        int idx = t + 256 * j;             // 0..8191
        int k = idx >> 7, o = idx & 127;
        dst[k * O_OUT + o] = Wt[o * 68 + k];
    }
}

// ---- Kernel B: main GEMM, 512 threads, 256 rows per block ----
__global__ __launch_bounds__(THREADS, 1)
void dw1d_kernel(const float* __restrict__ x,
                 const float* __restrict__ b,
                 float* __restrict__ out) {
    extern __shared__ float smem[];
    float* bias_sh = smem;                       // 128 floats
    float* Xsh = smem + 128;                     // [row][k] stride 68, 256 rows
    float* Wsh = smem + 128 + TILE_M * XSTR;     // [k][o]  stride 132

    const int t  = threadIdx.x;
    const int cg = t & 15;                       // col group (16 per warp-half)
    const int rg = t >> 4;                       // row group 0..31
    const int n0 = blockIdx.x * TILE_M;
    const int c  = blockIdx.y;

    if (t < O_OUT) bias_sh[t] = b[c * O_OUT + t];

    // stage x: coalesced LDG.128 -> Xsh[row][k]  (256 rows x 16 float4)
    {
        const float* xb = x + (size_t)c * K_IN;
#pragma unroll
        for (int j = 0; j < 8; ++j) {
            int idx = t + THREADS * j;     // 0..4095
            int row = idx >> 4, ku = idx & 15;
            float4 v = *(const float4*)(xb + (size_t)(n0 + row) * C_TOT * K_IN + 4 * ku);
            *(float4*)&Xsh[row * XSTR + 4 * ku] = v;
        }
    }
    // stage W (k-major): coalesced LDG.128 -> Wsh[k][o]
    {
        const float* wb = W2g + (size_t)c * K_IN * O_OUT;
#pragma unroll
        for (int j = 0; j < 4; ++j) {
            int idx = t + THREADS * j;     // 0..2047
            int k = idx >> 5, o4 = idx & 31;
            float4 v = *(const float4*)(wb + k * O_OUT + 4 * o4);
            *(float4*)&Wsh[k * WSTR + 4 * o4] = v;
        }
    }
    __syncthreads();

    // compute: rows r_i = rg + 32*i (i<8); cols {4cg..+3, 64+4cg..+3}
    unsigned long long acc[8][4];
#pragma unroll
    for (int i = 0; i < 8; ++i)
#pragma unroll
        for (int j = 0; j < 4; ++j)
            acc[i][j] = 0ULL;

    const float* wrow0 = &Wsh[4 * cg];
    const float* wrow1 = &Wsh[4 * cg + 64];

#pragma unroll 4
    for (int k = 0; k < K_IN; ++k) {
        float xs[8];
#pragma unroll
        for (int i = 0; i < 8; ++i)
            xs[i] = Xsh[(rg + 32 * i) * XSTR + k];   // half-warp broadcast, 1 wf

        ulonglong2 wv0 = *(const ulonglong2*)(wrow0 + k * WSTR);
        ulonglong2 wv1 = *(const ulonglong2*)(wrow1 + k * WSTR);
#pragma unroll
        for (int i = 0; i < 8; ++i) {
            unsigned long long xd = dup2(xs[i]);
            ffma2(acc[i][0], xd, wv0.x);
            ffma2(acc[i][1], xd, wv0.y);
            ffma2(acc[i][2], xd, wv1.x);
            ffma2(acc[i][3], xd, wv1.y);
        }
    }

    // epilogue: bias + 2 coalesced STG.128 per row
    float4 b0 = *(const float4*)&bias_sh[4 * cg];
    float4 b1 = *(const float4*)&bias_sh[64 + 4 * cg];

#pragma unroll
    for (int i = 0; i < 8; ++i) {
        int n = n0 + rg + 32 * i;
        float* orow = out + ((size_t)n * C_TOT + c) * O_OUT;
        float2 p0 = unpack2(acc[i][0]);
        float2 p1 = unpack2(acc[i][1]);
        float2 p2 = unpack2(acc[i][2]);
        float2 p3 = unpack2(acc[i][3]);
        float4 v0 = make_float4(p0.x + b0.x, p0.y + b0.y, p1.x + b0.z, p1.y + b0.w);
        float4 v1 = make_float4(p2.x + b1.x, p2.y + b1.y, p3.x + b1.z, p3.y + b1.w);
        *(float4*)&orow[4 * cg]      = v0;
        *(float4*)&orow[64 + 4 * cg] = v1;
    }
}

extern "C" void kernel_launch(void* const* d_in, const int* in_sizes, int n_in,
                              void* d_out, int out_size) {
    const float* x = (const float*)d_in[0];
    const float* W = (const float*)d_in[1];
    const float* b = (const float*)d_in[2];
    float* out = (float*)d_out;

    w_transpose<<<C_TOT, 256>>>(W);

    size_t smem_bytes = (size_t)(128 + TILE_M * XSTR + K_IN * WSTR) * sizeof(float); // 104192
    cudaFuncSetAttribute(dw1d_kernel,
                         cudaFuncAttributeMaxDynamicSharedMemorySize,
                         (int)smem_bytes);
    dim3 grid(N_TOT / TILE_M, C_TOT);
    dw1d_kernel<<<grid, THREADS, smem_bytes>>>(x, b, out);
}